// round 1
// baseline (speedup 1.0000x reference)
#include <cuda_runtime.h>
#include <math.h>

// Problem constants
#define T2       2          // two tensors: fake, real
#define BATCH    256
#define NSAMP    80000
#define NPERSEG  100
#define NFREQ    51
#define NSEG     800
#define COLS     (BATCH * NFREQ)   // 13056
#define SPB      5                 // segments per block in psd kernel (5*51=255 threads used)
#define SEGBLKS  (NSEG / SPB)      // 160

#define TWO_PI 6.28318530717958647692f

// Scratch: signed-clamp-log PSD, normalized in place. 2*800*13056*4 = 83.6 MB.
__device__ float  g_L[T2][NSEG][COLS];
__device__ float  g_sa[T2][NSEG];     // per-segment sum of squares (after normalize)
__device__ double g_acc[2];           // [0] = sum_k SF*SR, [1] = sum_k SF*SF

// ---------------------------------------------------------------------------
__global__ void zero_kernel() {
    if (threadIdx.x < 2) g_acc[threadIdx.x] = 0.0;
}

// ---------------------------------------------------------------------------
// Kernel A: Welch segments -> naive rDFT(100) -> |.|^2 -> signed clamped log.
// One block handles SPB=5 consecutive segments of one (tensor, batch) row.
// Thread tid < 255: segment tid/51, frequency tid%51.
__global__ __launch_bounds__(256) void psd_kernel(const float* __restrict__ fake,
                                                  const float* __restrict__ real_) {
    __shared__ float  xs[SPB * NPERSEG];  // windowed, clamped samples
    __shared__ float2 tw[NPERSEG];        // (cos, -sin)(2*pi*k/100)

    const int blk    = blockIdx.x;
    const int segblk = blk % SEGBLKS;
    const int b      = (blk / SEGBLKS) % BATCH;
    const int t      = blk / (SEGBLKS * BATCH);
    const float* __restrict__ src = (t == 0) ? fake : real_;
    const int tid = threadIdx.x;

    if (tid < NPERSEG) {
        float ang = TWO_PI * 0.01f * (float)tid;
        float s, c;
        sincosf(ang, &s, &c);
        tw[tid] = make_float2(c, -s);
    }
    const int base = b * NSAMP + segblk * (SPB * NPERSEG);
    for (int i = tid; i < SPB * NPERSEG; i += 256) {
        int n = i % NPERSEG;
        float w = 1.0f - cosf(TWO_PI * 0.01f * (float)n);  // hann(periodic)*2
        xs[i] = fmaxf(src[base + i], 1e-6f) * w;
    }
    __syncthreads();

    if (tid < SPB * NFREQ) {
        const int sl = tid / NFREQ;
        const int f  = tid - sl * NFREQ;
        const float* x = xs + sl * NPERSEG;

        float re = 0.0f, im = 0.0f;
        int idx = 0;  // (f*n) mod 100, tracked incrementally
        #pragma unroll 20
        for (int n = 0; n < NPERSEG; ++n) {
            float  v = x[n];
            float2 w = tw[idx];
            re = fmaf(v, w.x, re);
            im = fmaf(v, w.y, im);
            idx += f;
            if (idx >= NPERSEG) idx -= NPERSEG;
        }
        float psd = fmaf(re, re, im * im);
        float lx  = logf(psd);
        float sgn = (lx > 0.0f) ? 1.0f : ((lx < 0.0f) ? -1.0f : 0.0f);
        float out = sgn * fmaxf(fabsf(lx), 1e-6f);

        g_L[t][segblk * SPB + sl][b * NFREQ + f] = out;
    }
}

// ---------------------------------------------------------------------------
// Kernel B: per-segment normalization. Faithful to reference's reshape:
// group r (0..255) = flat indices { r + j*256 : j=0..50 } within the segment.
// min/max over the 51 group members, normalize in place, accumulate sum(x^2).
__global__ __launch_bounds__(256) void norm_kernel() {
    const int s = blockIdx.x % NSEG;
    const int t = blockIdx.x / NSEG;
    float* L = g_L[t][s];
    const int r = threadIdx.x;

    float v[NFREQ];
    float mn =  3.4e38f, mx = -3.4e38f;
    #pragma unroll
    for (int j = 0; j < NFREQ; ++j) {
        float x = L[j * 256 + r];
        v[j] = x;
        mn = fminf(mn, x);
        mx = fmaxf(mx, x);
    }
    const float inv = 1.0f / (mx - mn);
    float ssq = 0.0f;
    #pragma unroll
    for (int j = 0; j < NFREQ; ++j) {
        float x = (v[j] - mn) * inv;
        L[j * 256 + r] = x;
        ssq = fmaf(x, x, ssq);
    }

    __shared__ float red[256];
    red[r] = ssq;
    __syncthreads();
    for (int off = 128; off > 0; off >>= 1) {
        if (r < off) red[r] += red[r + off];
        __syncthreads();
    }
    if (r == 0) g_sa[t][s] = red[0];
}

// ---------------------------------------------------------------------------
// Kernel C: column sums over the segment axis, then dot products.
// Grid = COLS/256 = 51 blocks exactly.
__global__ __launch_bounds__(256) void colsum_kernel() {
    const int i = blockIdx.x * 256 + threadIdx.x;  // 0..13055
    float SF = 0.0f, SR = 0.0f;
    #pragma unroll 4
    for (int s = 0; s < NSEG; ++s) {
        SF += g_L[0][s][i];
        SR += g_L[1][s][i];
    }
    double d = (double)SF * (double)SR;
    double q = (double)SF * (double)SF;

    __shared__ double rd[256], rq[256];
    rd[threadIdx.x] = d;
    rq[threadIdx.x] = q;
    __syncthreads();
    for (int off = 128; off > 0; off >>= 1) {
        if (threadIdx.x < off) {
            rd[threadIdx.x] += rd[threadIdx.x + off];
            rq[threadIdx.x] += rq[threadIdx.x + off];
        }
        __syncthreads();
    }
    if (threadIdx.x == 0) {
        atomicAdd(&g_acc[0], rd[0]);
        atomicAdd(&g_acc[1], rq[0]);
    }
}

// ---------------------------------------------------------------------------
// Kernel D: reduce g_sa, combine everything into the two scalars.
__global__ __launch_bounds__(256) void final_kernel(float* __restrict__ out) {
    __shared__ double ra[256], rb[256];
    const int r = threadIdx.x;
    double sa = 0.0, sb = 0.0;
    for (int s = r; s < NSEG; s += 256) {
        sa += (double)g_sa[0][s];
        sb += (double)g_sa[1][s];
    }
    ra[r] = sa;
    rb[r] = sb;
    __syncthreads();
    for (int off = 128; off > 0; off >>= 1) {
        if (r < off) { ra[r] += ra[r + off]; rb[r] += rb[r + off]; }
        __syncthreads();
    }
    if (r == 0) {
        const double SA = ra[0], SB = rb[0];
        const double dot = g_acc[0], sf2 = g_acc[1];
        const double n  = (double)COLS;
        const double ns = (double)NSEG;
        const double m  = ns * (ns - 1.0) * 0.5;
        double psd_loss = (SA / ns + SB / ns - 2.0 * dot / (ns * ns)) / n;
        double fss      = (ns * SA - sf2) / (n * m);
        out[0] = (float)psd_loss;
        out[1] = (float)fss;
    }
}

// ---------------------------------------------------------------------------
extern "C" void kernel_launch(void* const* d_in, const int* in_sizes, int n_in,
                              void* d_out, int out_size) {
    const float* fake  = (const float*)d_in[0];
    const float* real_ = (const float*)d_in[1];
    float* out = (float*)d_out;

    zero_kernel<<<1, 32>>>();
    psd_kernel<<<T2 * BATCH * SEGBLKS, 256>>>(fake, real_);
    norm_kernel<<<T2 * NSEG, 256>>>();
    colsum_kernel<<<COLS / 256, 256>>>();
    final_kernel<<<1, 256>>>(out);
}

// round 2
// speedup vs baseline: 4.0127x; 4.0127x over previous
#include <cuda_runtime.h>
#include <math.h>
#include <float.h>

// Problem constants
#define T2       2
#define BATCH    256
#define NSAMP    80000
#define NPERSEG  100
#define NFREQ    51
#define NSEG     800
#define COLS     (BATCH * NFREQ)   // 13056
#define SPB      8                 // segments per psd block (8*64 = 512 threads)
#define SEGBLKS  (NSEG / SPB)      // 100
#define NSPB     8                 // segments per norm block
#define NORMBLKS (NSEG / NSPB)     // 100

#define TWO_PI 6.28318530717958647692f

// Scratch: signed-clamp-log PSD (unnormalized). 2*800*13056*4 = 83.6 MB.
__device__ float  g_L[T2][NSEG][COLS];
__device__ float  g_colsum[T2][COLS];  // column sums of normalized values
__device__ double g_saTot[T2];         // total sum of squares of normalized values

// ---------------------------------------------------------------------------
__global__ __launch_bounds__(256) void zero_kernel() {
    int i = blockIdx.x * 256 + threadIdx.x;
    if (i < T2 * COLS) ((float*)g_colsum)[i] = 0.0f;
    if (i < T2) g_saTot[i] = 0.0;
}

// ---------------------------------------------------------------------------
// Kernel A: Welch segments -> radix-10 rDFT(100) -> |.|^2 -> signed clamp log.
// Block: SPB=8 segments of one (tensor,batch) row; 64 threads per segment.
// Stage 1: thread u<60 -> Y[b][r] = sum_a x[10a+b] e^{-2pi i r a/10}, r=0..5.
// Stage 2: thread u<51 -> X[f] = sum_b e^{-2pi i f b/100} Y[b][f%10]
//          (f%10 > 5 handled via conjugate symmetry of Y, since x is real).
__global__ __launch_bounds__(512) void psd_kernel(const float* __restrict__ fake,
                                                  const float* __restrict__ real_) {
    __shared__ float  xs[SPB * NPERSEG];   // 3200 B
    __shared__ float2 Ysh[SPB][10][6];     // 3840 B
    __shared__ float2 tw[NPERSEG];         // (cos, -sin)(2*pi*k/100)

    const int blk    = blockIdx.x;
    const int segblk = blk % SEGBLKS;
    const int b      = (blk / SEGBLKS) % BATCH;
    const int t      = blk / (SEGBLKS * BATCH);
    const float* __restrict__ src = (t == 0) ? fake : real_;
    const int tid = threadIdx.x;

    if (tid < NPERSEG) {
        float s, c;
        sincosf(TWO_PI * 0.01f * (float)tid, &s, &c);
        tw[tid] = make_float2(c, -s);
    }
    const int base = b * NSAMP + segblk * (SPB * NPERSEG);
    for (int i = tid; i < SPB * NPERSEG; i += 512) {
        int n = i % NPERSEG;
        float w = 1.0f - cosf(TWO_PI * 0.01f * (float)n);   // hann(periodic)*2
        xs[i] = fmaxf(src[base + i], 1e-6f) * w;
    }
    __syncthreads();

    const int sl = tid >> 6;    // segment slot 0..7
    const int u  = tid & 63;

    // ---- Stage 1 ----
    if (u < 60) {
        const int bb = u / 6;
        const int r  = u % 6;
        const float* x = xs + sl * NPERSEG + bb;
        float yr = 0.0f, yi = 0.0f;
        int idx = 0;                       // (10*r*a) mod 100
        const int step = r * 10;
        #pragma unroll
        for (int a = 0; a < 10; ++a) {
            float  v = x[a * 10];
            float2 w = tw[idx];
            yr = fmaf(v, w.x, yr);
            yi = fmaf(v, w.y, yi);
            idx += step; if (idx >= 100) idx -= 100;
        }
        Ysh[sl][bb][r] = make_float2(yr, yi);
    }
    __syncthreads();

    // ---- Stage 2 ----
    if (u < NFREQ) {
        const int f = u;
        int r = f % 10;
        float cj = 1.0f;
        if (r > 5) { r = 10 - r; cj = -1.0f; }
        float Xr = 0.0f, Xi = 0.0f;
        int idx = 0;                       // (f*b) mod 100
        #pragma unroll
        for (int bb = 0; bb < 10; ++bb) {
            float2 y = Ysh[sl][bb][r];
            float  yi2 = y.y * cj;
            float2 e = tw[idx];
            Xr = fmaf(e.x, y.x, Xr);
            Xr = fmaf(-e.y, yi2, Xr);
            Xi = fmaf(e.x, yi2, Xi);
            Xi = fmaf(e.y, y.x, Xi);
            idx += f; if (idx >= 100) idx -= 100;
        }
        float psd = fmaf(Xr, Xr, Xi * Xi);
        float lx  = logf(psd);
        float sgn = (lx > 0.0f) ? 1.0f : ((lx < 0.0f) ? -1.0f : 0.0f);
        float outv = sgn * fmaxf(fabsf(lx), 1e-6f);
        g_L[t][segblk * SPB + sl][b * NFREQ + f] = outv;
    }
}

// ---------------------------------------------------------------------------
// Kernel B: fused per-segment normalize (group r = {flat[j*256+r]}) + column
// sums + sum-of-squares. Normalized values live only in registers.
__global__ __launch_bounds__(256) void norm_kernel() {
    const int blk = blockIdx.x;            // 0 .. 2*NORMBLKS-1
    const int t   = blk / NORMBLKS;
    const int c   = blk % NORMBLKS;
    const int r   = threadIdx.x;

    float csum[NFREQ];
    #pragma unroll
    for (int j = 0; j < NFREQ; ++j) csum[j] = 0.0f;
    float ssq = 0.0f;

    for (int k = 0; k < NSPB; ++k) {
        const int s = c * NSPB + k;
        const float* __restrict__ L = g_L[t][s];
        float v[NFREQ];
        float mn = FLT_MAX, mx = -FLT_MAX;
        #pragma unroll
        for (int j = 0; j < NFREQ; ++j) {
            float x = L[j * 256 + r];
            v[j] = x;
            mn = fminf(mn, x);
            mx = fmaxf(mx, x);
        }
        const float inv = 1.0f / (mx - mn);
        #pragma unroll
        for (int j = 0; j < NFREQ; ++j) {
            float x = (v[j] - mn) * inv;
            csum[j] += x;
            ssq = fmaf(x, x, ssq);
        }
    }

    #pragma unroll
    for (int j = 0; j < NFREQ; ++j)
        atomicAdd(&g_colsum[t][j * 256 + r], csum[j]);

    __shared__ float red[256];
    red[r] = ssq;
    __syncthreads();
    for (int off = 128; off > 0; off >>= 1) {
        if (r < off) red[r] += red[r + off];
        __syncthreads();
    }
    if (r == 0) atomicAdd(&g_saTot[t], (double)red[0]);
}

// ---------------------------------------------------------------------------
// Kernel C: single block — column-sum dot products + final combine.
__global__ __launch_bounds__(256) void final_kernel(float* __restrict__ out) {
    const int r = threadIdx.x;
    double dot = 0.0, sf2 = 0.0;
    for (int i = r; i < COLS; i += 256) {
        double SF = (double)g_colsum[0][i];
        double SR = (double)g_colsum[1][i];
        dot += SF * SR;
        sf2 += SF * SF;
    }
    __shared__ double rd[256], rq[256];
    rd[r] = dot; rq[r] = sf2;
    __syncthreads();
    for (int off = 128; off > 0; off >>= 1) {
        if (r < off) { rd[r] += rd[r + off]; rq[r] += rq[r + off]; }
        __syncthreads();
    }
    if (r == 0) {
        const double SA = g_saTot[0], SB = g_saTot[1];
        const double n  = (double)COLS;
        const double ns = (double)NSEG;
        const double m  = ns * (ns - 1.0) * 0.5;
        double psd_loss = (SA / ns + SB / ns - 2.0 * rd[0] / (ns * ns)) / n;
        double fss      = (ns * SA - rq[0]) / (n * m);
        out[0] = (float)psd_loss;
        out[1] = (float)fss;
    }
}

// ---------------------------------------------------------------------------
extern "C" void kernel_launch(void* const* d_in, const int* in_sizes, int n_in,
                              void* d_out, int out_size) {
    const float* fake  = (const float*)d_in[0];
    const float* real_ = (const float*)d_in[1];
    float* out = (float*)d_out;

    zero_kernel<<<(T2 * COLS + 255) / 256, 256>>>();
    psd_kernel<<<T2 * BATCH * SEGBLKS, 512>>>(fake, real_);
    norm_kernel<<<T2 * NORMBLKS, 256>>>();
    final_kernel<<<1, 256>>>(out);
}

// round 3
// speedup vs baseline: 6.7504x; 1.6823x over previous
#include <cuda_runtime.h>
#include <math.h>
#include <float.h>

#define T2       2
#define BATCH    256
#define NSAMP    80000
#define NPERSEG  100
#define NFREQ    51
#define NSEG     800
#define COLS     (BATCH * NFREQ)         // 13056 = 51*256
#define NSPB     8
#define NORMBLKS (NSEG / NSPB)           // 100
#define IPB      24                      // instances per psd block (8 warps x 3)
#define TOTAL    (T2 * NSEG * BATCH)     // 409600
#define PSDBLKS  ((TOTAL + IPB - 1) / IPB)

#define TWO_PI 6.28318530717958647692f

// w10^k = e^{-2*pi*i*k/10} = (C10[k], -S10[k]) — compile-time immediates
__device__ constexpr float C10[10] = {
     1.0f,  0.80901699437494745f,  0.30901699437494745f, -0.30901699437494745f,
    -0.80901699437494745f, -1.0f, -0.80901699437494745f, -0.30901699437494745f,
     0.30901699437494745f,  0.80901699437494745f };
__device__ constexpr float S10[10] = {
     0.0f,  0.58778525229247314f,  0.95105651629515353f,  0.95105651629515353f,
     0.58778525229247314f,  0.0f, -0.58778525229247314f, -0.95105651629515353f,
    -0.95105651629515353f, -0.58778525229247314f };

// Scratch: signed-clamp-log PSD (unnormalized). 83.6 MB.
__device__ float  g_L[T2][NSEG][COLS];
__device__ float  g_colsum[T2][COLS];
__device__ double g_saTot[T2];
__device__ double g_acc[2];   // [0]=sum SF*SR, [1]=sum SF*SF

__device__ __forceinline__ float sclog(float p) {
    float lx = logf(p);
    float s  = (lx > 0.0f) ? 1.0f : ((lx < 0.0f) ? -1.0f : 0.0f);
    return s * fmaxf(fabsf(lx), 1e-6f);
}

// ---------------------------------------------------------------------------
__global__ __launch_bounds__(256) void zero_kernel() {
    int i = blockIdx.x * 256 + threadIdx.x;
    if (i < T2 * COLS) ((float*)g_colsum)[i] = 0.0f;
    if (i < T2) g_saTot[i] = 0.0;
    if (i < 2)  g_acc[i] = 0.0;
}

// ---------------------------------------------------------------------------
// Kernel A: Welch -> 10x10 Cooley-Tukey rDFT(100) -> |.|^2 -> signed clamp log.
// Warp = 3 segment-instances, 10 active lanes each. Stage1 lane=q (sample
// phase), stage2 lane=m (output class). Inner twiddles are immediates.
__global__ __launch_bounds__(256) void psd_kernel(const float* __restrict__ fake,
                                                  const float* __restrict__ real_) {
    __shared__ float  wnd[NPERSEG];
    __shared__ float2 tws[NPERSEG];          // e^{-2 pi i k/100}
    __shared__ float  xs[IPB][NPERSEG];
    __shared__ float2 Ysh[IPB][10][6];
    __shared__ float  psd_s[IPB][NFREQ];

    const int tid = threadIdx.x;
    if (tid < NPERSEG) {
        float s, c;
        sincosf(TWO_PI * 0.01f * (float)tid, &s, &c);
        tws[tid] = make_float2(c, -s);
        wnd[tid] = 1.0f - c;                 // hann(periodic)*2
    }
    __syncthreads();

    const int warp = tid >> 5, lane = tid & 31;
    const int base_inst = warp * 3;
    const long gbase = (long)blockIdx.x * IPB + base_inst;

    // ---- stage 0: coalesced load + clamp + window into smem ----
    #pragma unroll
    for (int k = 0; k < 3; ++k) {
        long g = gbase + k;
        if (g >= TOTAL) break;
        int t   = (int)(g / (NSEG * BATCH));
        int rem = (int)(g - (long)t * (NSEG * BATCH));
        int seg = rem / BATCH, b = rem - seg * BATCH;
        const float* __restrict__ src =
            ((t == 0) ? fake : real_) + (size_t)b * NSAMP + (size_t)seg * NPERSEG;
        for (int i = lane; i < NPERSEG; i += 32)
            xs[base_inst + k][i] = fmaxf(src[i], 1e-6f) * wnd[i];
    }
    __syncwarp();

    const int  ik   = lane / 10;             // 0..2
    const int  role = lane - ik * 10;        // 0..9
    const int  inst = base_inst + ik;
    const bool act  = (lane < 30) && (gbase + ik < TOTAL);

    // ---- stage 1: Y[q][r] = sum_a x[10a+q] w10^{ra}, r=0..5 ----
    if (act) {
        float xr[10];
        #pragma unroll
        for (int a = 0; a < 10; ++a) xr[a] = xs[inst][a * 10 + role];
        #pragma unroll
        for (int r = 0; r < 6; ++r) {
            float re = 0.0f, im = 0.0f;
            #pragma unroll
            for (int a = 0; a < 10; ++a) {
                const int k = (r * a) % 10;
                re = fmaf(xr[a],  C10[k], re);
                im = fmaf(xr[a], -S10[k], im);
            }
            Ysh[inst][role][r] = make_float2(re, im);
        }
    }
    __syncwarp();

    // ---- stage 2: Z[q] = tw100[m q] * Y~[q];  X[10j+m] = sum_q w10^{jq} Z[q]
    if (act) {
        const int   m  = role;
        const int   c  = (m <= 5) ? m : 10 - m;
        const float cj = (m <= 5) ? 1.0f : -1.0f;
        float Zr[10], Zi[10];
        #pragma unroll
        for (int q = 0; q < 10; ++q) {
            float2 y = Ysh[inst][q][c];
            float  yi = y.y * cj;
            float2 e = tws[m * q];
            Zr[q] = fmaf(e.x, y.x, -e.y * yi);
            Zi[q] = fmaf(e.x, yi,   e.y * y.x);
        }
        #pragma unroll
        for (int j = 0; j < 5; ++j) {
            float Xr = 0.0f, Xi = 0.0f;
            #pragma unroll
            for (int q = 0; q < 10; ++q) {
                const int k = (j * q) % 10;
                Xr = fmaf(Zr[q],  C10[k], Xr);
                Xr = fmaf(Zi[q],  S10[k], Xr);
                Xi = fmaf(Zi[q],  C10[k], Xi);
                Xi = fmaf(Zr[q], -S10[k], Xi);
            }
            psd_s[inst][m + 10 * j] = sclog(fmaf(Xr, Xr, Xi * Xi));
        }
        if (m == 0) {                         // f = 50: w10^{5q} = ±1
            float Xr = 0.0f, Xi = 0.0f;
            #pragma unroll
            for (int q = 0; q < 10; ++q) {
                const int k = (5 * q) % 10;
                Xr = fmaf(Zr[q], C10[k], Xr);
                Xi = fmaf(Zi[q], C10[k], Xi);
            }
            psd_s[inst][50] = sclog(fmaf(Xr, Xr, Xi * Xi));
        }
    }
    __syncwarp();

    // ---- stage 3: coalesced write-out ----
    for (int i = lane; i < 3 * NFREQ; i += 32) {
        int k = i / NFREQ, f = i - k * NFREQ;
        long gg = gbase + k;
        if (gg >= TOTAL) break;
        int t   = (int)(gg / (NSEG * BATCH));
        int rem = (int)(gg - (long)t * (NSEG * BATCH));
        int seg = rem / BATCH, b = rem - seg * BATCH;
        g_L[t][seg][b * NFREQ + f] = psd_s[base_inst + k][f];
    }
}

// ---------------------------------------------------------------------------
// Kernel B: fused per-segment normalize + column sums + sum of squares.
__global__ __launch_bounds__(256) void norm_kernel() {
    const int blk = blockIdx.x;
    const int t   = blk / NORMBLKS;
    const int c   = blk % NORMBLKS;
    const int r   = threadIdx.x;

    float csum[NFREQ];
    #pragma unroll
    for (int j = 0; j < NFREQ; ++j) csum[j] = 0.0f;
    float ssq = 0.0f;

    for (int k = 0; k < NSPB; ++k) {
        const int s = c * NSPB + k;
        const float* __restrict__ L = g_L[t][s];
        float v[NFREQ];
        float mn = FLT_MAX, mx = -FLT_MAX;
        #pragma unroll
        for (int j = 0; j < NFREQ; ++j) {
            float x = L[j * 256 + r];
            v[j] = x;
            mn = fminf(mn, x);
            mx = fmaxf(mx, x);
        }
        const float inv = 1.0f / (mx - mn);
        #pragma unroll
        for (int j = 0; j < NFREQ; ++j) {
            float x = (v[j] - mn) * inv;
            csum[j] += x;
            ssq = fmaf(x, x, ssq);
        }
    }

    #pragma unroll
    for (int j = 0; j < NFREQ; ++j)
        atomicAdd(&g_colsum[t][j * 256 + r], csum[j]);

    __shared__ float red[256];
    red[r] = ssq;
    __syncthreads();
    for (int off = 128; off > 0; off >>= 1) {
        if (r < off) red[r] += red[r + off];
        __syncthreads();
    }
    if (r == 0) atomicAdd(&g_saTot[t], (double)red[0]);
}

// ---------------------------------------------------------------------------
// Kernel C: parallel dot products over column sums. grid = 51 (COLS/256).
__global__ __launch_bounds__(256) void dot_kernel() {
    const int i = blockIdx.x * 256 + threadIdx.x;
    double SF = (double)g_colsum[0][i];
    double SR = (double)g_colsum[1][i];
    double d = SF * SR, q = SF * SF;

    __shared__ double rd[256], rq[256];
    rd[threadIdx.x] = d; rq[threadIdx.x] = q;
    __syncthreads();
    for (int off = 128; off > 0; off >>= 1) {
        if (threadIdx.x < off) {
            rd[threadIdx.x] += rd[threadIdx.x + off];
            rq[threadIdx.x] += rq[threadIdx.x + off];
        }
        __syncthreads();
    }
    if (threadIdx.x == 0) {
        atomicAdd(&g_acc[0], rd[0]);
        atomicAdd(&g_acc[1], rq[0]);
    }
}

// ---------------------------------------------------------------------------
__global__ void final_kernel(float* __restrict__ out) {
    if (threadIdx.x == 0) {
        const double SA = g_saTot[0], SB = g_saTot[1];
        const double n  = (double)COLS;
        const double ns = (double)NSEG;
        const double m  = ns * (ns - 1.0) * 0.5;
        out[0] = (float)((SA / ns + SB / ns - 2.0 * g_acc[0] / (ns * ns)) / n);
        out[1] = (float)((ns * SA - g_acc[1]) / (n * m));
    }
}

// ---------------------------------------------------------------------------
extern "C" void kernel_launch(void* const* d_in, const int* in_sizes, int n_in,
                              void* d_out, int out_size) {
    const float* fake  = (const float*)d_in[0];
    const float* real_ = (const float*)d_in[1];
    float* out = (float*)d_out;

    zero_kernel<<<(T2 * COLS + 255) / 256, 256>>>();
    psd_kernel<<<PSDBLKS, 256>>>(fake, real_);
    norm_kernel<<<T2 * NORMBLKS, 256>>>();
    dot_kernel<<<COLS / 256, 256>>>();
    final_kernel<<<1, 32>>>(out);
}